// round 16
// baseline (speedup 1.0000x reference)
#include <cuda_runtime.h>
#include <math.h>

#define DIM       512
#define NBLK      512          // k1 grid: 32 regs * 512 thr -> 4 blocks/SM, single wave
#define THREADS_X 128          // float4 lanes covering DIM
#define THREADS_Y 4

// Global accumulators: per-dim running sums, updated by fire-and-forget
// fp32 atomicAdd (REDG) from k1 blocks. 512 + 512 floats = 4 KB.
// Zero at module load; k_final re-zeroes after consuming, so every
// kernel_launch execution starts from zero.
__device__ float g_accP[DIM];
__device__ float g_accQ[DIM];

// ---------------------------------------------------------------------------
// Kernel 1 — R6's banked streaming configuration (71.4% DRAM / 5.65 TB/s):
// plain float4 loads, unroll 8, computed index, uniform 128 rows per block.
// Finish: instead of writing per-block partial rows to scratch (measured
// ~9-12 us to read back in EVERY configuration tried), each block's 128
// y==0 threads do 8 fp32 atomicAdds (REDG, no return) into the per-dim
// accumulators. ~0.2-0.5 us of L2-atomic traffic, overlapped across blocks.
// ---------------------------------------------------------------------------
__global__ void __launch_bounds__(THREADS_X * THREADS_Y)
k1_reduce(const float* __restrict__ z, int rows_per_blk) {
    const int x = threadIdx.x;        // 0..127 : float4 lane -> dims 4x..4x+3
    const int y = threadIdx.y;        // 0..3   : row interleave
    const int b = blockIdx.x;

    const float4* __restrict__ zp = reinterpret_cast<const float4*>(z);

    float4 P = make_float4(0.f, 0.f, 0.f, 0.f);
    float4 Q = make_float4(0.f, 0.f, 0.f, 0.f);

    const long long row0 = (long long)b * rows_per_blk + y;
    const int iters = rows_per_blk / THREADS_Y;   // 32

    #pragma unroll 8
    for (int i = 0; i < iters; ++i) {
        float4 v = zp[(row0 + (long long)i * THREADS_Y) * (DIM / 4) + x];
        P.x += v.x; P.y += v.y; P.z += v.z; P.w += v.w;
        Q.x = fmaf(v.x, v.x, Q.x);
        Q.y = fmaf(v.y, v.y, Q.y);
        Q.z = fmaf(v.z, v.z, Q.z);
        Q.w = fmaf(v.w, v.w, Q.w);
    }

    __shared__ float4 sP[THREADS_Y][THREADS_X];
    __shared__ float4 sQ[THREADS_Y][THREADS_X];
    sP[y][x] = P;
    sQ[y][x] = Q;
    __syncthreads();

    if (y == 0) {
        float4 p = sP[0][x];
        float4 q = sQ[0][x];
        #pragma unroll
        for (int j = 1; j < THREADS_Y; ++j) {
            float4 pj = sP[j][x];
            float4 qj = sQ[j][x];
            p.x += pj.x; p.y += pj.y; p.z += pj.z; p.w += pj.w;
            q.x += qj.x; q.y += qj.y; q.z += qj.z; q.w += qj.w;
        }
        const int d0 = x * 4;
        atomicAdd(&g_accP[d0 + 0], p.x);
        atomicAdd(&g_accP[d0 + 1], p.y);
        atomicAdd(&g_accP[d0 + 2], p.z);
        atomicAdd(&g_accP[d0 + 3], p.w);
        atomicAdd(&g_accQ[d0 + 0], q.x);
        atomicAdd(&g_accQ[d0 + 1], q.y);
        atomicAdd(&g_accQ[d0 + 2], q.z);
        atomicAdd(&g_accQ[d0 + 3], q.w);
    }
}

// ---------------------------------------------------------------------------
// Final kernel — 1 block, 512 threads, one dim each. Reads the 4 KB
// accumulators, runs the fp32 closed-form epilogue, block-reduces, writes
// the scalar, then zeroes the accumulators for the next replay.
//
// Per dim d (s = pv - pc):
//   sum_t log(2*pi*var_t)      = T*log2pi + (T-1)*log(s) + log(s + T*pc)
//   sum_t (z_t-mu_t)^2 / var_t = (Q - pc/(s+T*pc) * P^2) / s
//   P = Sz - T*mu0, Q = Szz - 2*mu0*Sz + T*mu0^2;  c0 = -0.5*T*log2pi (host).
// ---------------------------------------------------------------------------
__global__ void __launch_bounds__(DIM)
k_final(const float* __restrict__ var_vbl,
        const float* __restrict__ corr_vbl,
        const float* __restrict__ prior_mu,
        float* __restrict__ out,
        int T, float c0) {
    const int d = threadIdx.x;            // 0..511

    const float Sz  = g_accP[d];
    const float Szz = g_accQ[d];

    const float Tn  = (float)T;
    const float x1  = var_vbl[d];
    const float x2  = corr_vbl[d];
    const float mu0 = prior_mu[d];

    const float sp = (x1 > 20.0f) ? x1 : log1pf(expf(x1));
    const float pv = sp * sp;
    const float sg = 1.0f / (1.0f + expf(-x2));
    const float pc = sg * pv;
    const float s  = pv - pc;

    const float Pd = Sz - Tn * mu0;
    const float Qd = Szz - 2.0f * mu0 * Sz + Tn * mu0 * mu0;

    const float denom = s + Tn * pc;
    const float quad  = (Qd - (pc / denom) * Pd * Pd) / s;

    __shared__ float red[DIM];
    red[d] = c0 - 0.5f * ((Tn - 1.0f) * logf(s) + logf(denom) + quad);

    // Reset accumulators for the next replay (each thread owns its slot and
    // has already consumed it; no sync needed before the overwrite).
    g_accP[d] = 0.f;
    g_accQ[d] = 0.f;

    __syncthreads();
    #pragma unroll
    for (int off = DIM / 2; off > 0; off >>= 1) {
        if (d < off) red[d] += red[d + off];
        __syncthreads();
    }
    if (d == 0) out[0] = red[0];
}

// ---------------------------------------------------------------------------
extern "C" void kernel_launch(void* const* d_in, const int* in_sizes, int n_in,
                              void* d_out, int out_size) {
    const float* z_rest   = (const float*)d_in[0];   // [T, 512]
    const float* var_vbl  = (const float*)d_in[1];   // [512]
    const float* corr_vbl = (const float*)d_in[2];   // [512]
    const float* prior_mu = (const float*)d_in[3];   // [512]
    float* out = (float*)d_out;

    const int T = in_sizes[0] / DIM;                 // 65536
    const int rows_per_blk = T / NBLK;               // 128

    const double LOG_2PI = 1.8378770664093454835606594728112;
    const float c0 = (float)(-0.5 * (double)T * LOG_2PI);

    dim3 blk1(THREADS_X, THREADS_Y);
    k1_reduce<<<NBLK, blk1>>>(z_rest, rows_per_blk);
    k_final<<<1, DIM>>>(var_vbl, corr_vbl, prior_mu, out, T, c0);
}

// round 17
// speedup vs baseline: 1.3965x; 1.3965x over previous
#include <cuda_runtime.h>
#include <math.h>

#define DIM       512
#define NBLK      512          // k1 grid: 32 regs * 512 thr -> 4 blocks/SM, single wave
#define THREADS_X 128          // float4 lanes covering DIM
#define THREADS_Y 4
#define NTAIL     32           // tail grid
#define NPAIR     (DIM / 2)    // 256 dim-pairs

// Level-1 partials: per (k1-block, dim-pair) float4 {P0,Q0,P1,Q1}. 512*256*16B = 2 MB.
__device__ float4 g_scratch[NBLK * NPAIR];
// Level-2 partials: 32 * 256 * 16B = 128 KB.
__device__ float4 g_scratch2[NTAIL * NPAIR];
// Completion counter (zero-initialized at load; reset by final tail block).
__device__ int g_cnt_fin;

// ---------------------------------------------------------------------------
// Kernel 1 — R6/R13 banked streaming configuration (71.4% DRAM): unroll 8,
// computed index, uniform 128 rows/block. ONE change vs R13: z loads are
// __ldcs (evict-first). The stream is read-once, so keeping it out of L2
// preserves the 2 MB of partials for the tail kernel (R13's tail read them
// from DRAM at 244 GB/s because the stream had evicted them).
// ---------------------------------------------------------------------------
__global__ void __launch_bounds__(THREADS_X * THREADS_Y)
k1_reduce(const float* __restrict__ z, int rows_per_blk) {
    const int x = threadIdx.x;        // 0..127 : float4 lane -> dims 4x..4x+3
    const int y = threadIdx.y;        // 0..3   : row interleave
    const int b = blockIdx.x;

    const float4* __restrict__ zp = reinterpret_cast<const float4*>(z);

    float4 P = make_float4(0.f, 0.f, 0.f, 0.f);
    float4 Q = make_float4(0.f, 0.f, 0.f, 0.f);

    const long long row0 = (long long)b * rows_per_blk + y;
    const int iters = rows_per_blk / THREADS_Y;   // 32

    #pragma unroll 8
    for (int i = 0; i < iters; ++i) {
        float4 v = __ldcs(&zp[(row0 + (long long)i * THREADS_Y) * (DIM / 4) + x]);
        P.x += v.x; P.y += v.y; P.z += v.z; P.w += v.w;
        Q.x = fmaf(v.x, v.x, Q.x);
        Q.y = fmaf(v.y, v.y, Q.y);
        Q.z = fmaf(v.z, v.z, Q.z);
        Q.w = fmaf(v.w, v.w, Q.w);
    }

    __shared__ float4 sP[THREADS_Y][THREADS_X];
    __shared__ float4 sQ[THREADS_Y][THREADS_X];
    sP[y][x] = P;
    sQ[y][x] = Q;
    __syncthreads();

    if (y == 0) {
        float4 p = sP[0][x];
        float4 q = sQ[0][x];
        #pragma unroll
        for (int j = 1; j < THREADS_Y; ++j) {
            float4 pj = sP[j][x];
            float4 qj = sQ[j][x];
            p.x += pj.x; p.y += pj.y; p.z += pj.z; p.w += pj.w;
            q.x += qj.x; q.y += qj.y; q.z += qj.z; q.w += qj.w;
        }
        float4* __restrict__ outp = &g_scratch[b * NPAIR + 2 * x];
        outp[0] = make_float4(p.x, q.x, p.y, q.y);
        outp[1] = make_float4(p.z, q.z, p.w, q.w);
    }
}

// ---------------------------------------------------------------------------
// Tail kernel — identical to R13. With the z-stream now evict-first, the
// level-1 reads below hit L2 (234 cyc) instead of DRAM (577+ cyc).
//
// 32 blocks x 1024 threads: j = dim-pair (0..255), sl = row-slice (0..3).
// Level 1: each block reduces 16 partial rows (4 per slice, batched x4),
//          smem slice-combine, write one level-2 row.
// Level 2: last-elected block reduces the 32 level-2 rows, then the fp32
//          closed-form epilogue:
//   per dim d (s = pv - pc):
//   sum_t log(2*pi*var_t)      = T*log2pi + (T-1)*log(s) + log(s + T*pc)
//   sum_t (z_t-mu_t)^2 / var_t = (Q - pc/(s+T*pc) * P^2) / s
//   P = Sz - T*mu0, Q = Szz - 2*mu0*Sz + T*mu0^2;  c0 = -0.5*T*log2pi (host).
// ---------------------------------------------------------------------------
__global__ void __launch_bounds__(1024)
k_tail(const float* __restrict__ var_vbl,
       const float* __restrict__ corr_vbl,
       const float* __restrict__ prior_mu,
       float* __restrict__ out,
       int T, float c0) {
    const int tid = threadIdx.x;          // 0..1023
    const int j   = tid & (NPAIR - 1);    // dim-pair 0..255 -> dims 2j, 2j+1
    const int sl  = tid >> 8;             // row-slice 0..3
    const int g   = blockIdx.x;           // 0..31

    __shared__ float4 s1[4][NPAIR];       // 16 KB slice-combine buffer

    // ---- Level 1: 16 rows per block, 4 per slice, batched loads -----------
    {
        const float4* __restrict__ base =
            &g_scratch[(g * 16 + sl * 4) * NPAIR + j];
        float4 v0 = base[0 * NPAIR];
        float4 v1 = base[1 * NPAIR];
        float4 v2 = base[2 * NPAIR];
        float4 v3 = base[3 * NPAIR];
        float4 a;
        a.x = (v0.x + v1.x) + (v2.x + v3.x);
        a.y = (v0.y + v1.y) + (v2.y + v3.y);
        a.z = (v0.z + v1.z) + (v2.z + v3.z);
        a.w = (v0.w + v1.w) + (v2.w + v3.w);
        s1[sl][j] = a;
    }
    __syncthreads();

    if (sl == 0) {
        float4 a = s1[0][j], b1 = s1[1][j], b2 = s1[2][j], b3 = s1[3][j];
        a.x = (a.x + b1.x) + (b2.x + b3.x);
        a.y = (a.y + b1.y) + (b2.y + b3.y);
        a.z = (a.z + b1.z) + (b2.z + b3.z);
        a.w = (a.w + b1.w) + (b2.w + b3.w);
        g_scratch2[g * NPAIR + j] = a;
    }
    __threadfence();
    __syncthreads();

    // ---- Elect last block -------------------------------------------------
    __shared__ int s_fin;
    if (tid == 0) {
        int done = atomicAdd(&g_cnt_fin, 1);
        s_fin = (done == NTAIL - 1);
    }
    __syncthreads();
    if (!s_fin) return;

    __threadfence();                       // acquire level-2 partials

    // ---- Level 2: 32 rows, 8 per slice, batched loads (L2-hot) ------------
    {
        const float4* __restrict__ base = &g_scratch2[(sl * 8) * NPAIR + j];
        float4 v0 = base[0 * NPAIR];
        float4 v1 = base[1 * NPAIR];
        float4 v2 = base[2 * NPAIR];
        float4 v3 = base[3 * NPAIR];
        float4 v4 = base[4 * NPAIR];
        float4 v5 = base[5 * NPAIR];
        float4 v6 = base[6 * NPAIR];
        float4 v7 = base[7 * NPAIR];
        float4 a;
        a.x = ((v0.x + v1.x) + (v2.x + v3.x)) + ((v4.x + v5.x) + (v6.x + v7.x));
        a.y = ((v0.y + v1.y) + (v2.y + v3.y)) + ((v4.y + v5.y) + (v6.y + v7.y));
        a.z = ((v0.z + v1.z) + (v2.z + v3.z)) + ((v4.z + v5.z) + (v6.z + v7.z));
        a.w = ((v0.w + v1.w) + (v2.w + v3.w)) + ((v4.w + v5.w) + (v6.w + v7.w));
        s1[sl][j] = a;
    }
    __syncthreads();

    __shared__ float red[NPAIR];
    if (sl == 0) {
        float4 a = s1[0][j], b1 = s1[1][j], b2 = s1[2][j], b3 = s1[3][j];
        a.x = (a.x + b1.x) + (b2.x + b3.x);
        a.y = (a.y + b1.y) + (b2.y + b3.y);
        a.z = (a.z + b1.z) + (b2.z + b3.z);
        a.w = (a.w + b1.w) + (b2.w + b3.w);

        // ---- Epilogue (fp32 closed form) ---------------------------------
        const float Tn = (float)T;
        float lkd_pair = 0.f;
        #pragma unroll
        for (int w = 0; w < 2; ++w) {
            const int d = 2 * j + w;
            const float Sz  = w ? a.z : a.x;
            const float Szz = w ? a.w : a.y;

            const float x1  = var_vbl[d];
            const float x2  = corr_vbl[d];
            const float mu0 = prior_mu[d];

            const float sp = (x1 > 20.0f) ? x1 : log1pf(expf(x1));
            const float pv = sp * sp;
            const float sg = 1.0f / (1.0f + expf(-x2));
            const float pc = sg * pv;
            const float s  = pv - pc;

            const float Pd = Sz - Tn * mu0;
            const float Qd = Szz - 2.0f * mu0 * Sz + Tn * mu0 * mu0;

            const float denom = s + Tn * pc;
            const float quad  = (Qd - (pc / denom) * Pd * Pd) / s;

            lkd_pair += c0 - 0.5f * ((Tn - 1.0f) * logf(s) + logf(denom) + quad);
        }
        red[j] = lkd_pair;
    }
    __syncthreads();

    #pragma unroll
    for (int off = NPAIR / 2; off > 0; off >>= 1) {
        if (tid < off) red[tid] += red[tid + off];
        __syncthreads();
    }

    if (tid == 0) {
        out[0] = red[0];
        g_cnt_fin = 0;     // reset for next graph replay (all blocks arrived)
    }
}

// ---------------------------------------------------------------------------
extern "C" void kernel_launch(void* const* d_in, const int* in_sizes, int n_in,
                              void* d_out, int out_size) {
    const float* z_rest   = (const float*)d_in[0];   // [T, 512]
    const float* var_vbl  = (const float*)d_in[1];   // [512]
    const float* corr_vbl = (const float*)d_in[2];   // [512]
    const float* prior_mu = (const float*)d_in[3];   // [512]
    float* out = (float*)d_out;

    const int T = in_sizes[0] / DIM;                 // 65536
    const int rows_per_blk = T / NBLK;               // 128

    const double LOG_2PI = 1.8378770664093454835606594728112;
    const float c0 = (float)(-0.5 * (double)T * LOG_2PI);

    dim3 blk1(THREADS_X, THREADS_Y);
    k1_reduce<<<NBLK, blk1>>>(z_rest, rows_per_blk);
    k_tail<<<NTAIL, 1024>>>(var_vbl, corr_vbl, prior_mu, out, T, c0);
}